// round 1
// baseline (speedup 1.0000x reference)
#include <cuda_runtime.h>
#include <cuda_bf16.h>

#define N_OBJ 32
#define GSIZE 3
#define NFILT 16
#define RDIM 16
#define BATCH 32
#define NQ 512
#define NG 4960                 // C(32,3)
#define NCOL 512                // BATCH * NFILT
#define OUT_ELEMS (BATCH * NQ * NFILT)   // 262144
#define NSPLIT 4
#define KTILES 310              // 4960 / 16

// ---------------- scratch (device globals; no allocations allowed) ------------
__device__ float  g_RC[NG * NCOL];        // rel_conv laid out [g][b*16+f]  (10.2 MB)
__device__ float  g_W [NQ * NG];          // softmax weights [q][g]          (10.2 MB)
__device__ float  g_part[NSPLIT * NQ * NCOL]; // split-K partials            (4 MB)
__device__ int4   g_idx[NG];              // combination table (i<j<k)

// ---------------- packed fp32x2 helpers --------------------------------------
__device__ __forceinline__ void ffma2(unsigned long long &acc,
                                      unsigned long long a,
                                      unsigned long long b) {
    asm("fma.rn.f32x2 %0, %1, %2, %0;" : "+l"(acc) : "l"(a), "l"(b));
}
__device__ __forceinline__ unsigned long long dup2(float x) {
    unsigned long long r;
    asm("mov.b64 %0, {%1, %1};" : "=l"(r) : "f"(x));
    return r;
}
__device__ __forceinline__ float2 unpk2(unsigned long long v) {
    float2 r;
    asm("mov.b64 {%0, %1}, %2;" : "=f"(r.x), "=f"(r.y) : "l"(v));
    return r;
}

// ---------------- kernel 0: lexicographic unrank of C(32,3) ------------------
__global__ void k_idx() {
    int g = blockIdx.x * blockDim.x + threadIdx.x;
    if (g >= NG) return;
    int r = g, i = 0;
    for (; i < 30; ++i) {
        int c = (31 - i) * (30 - i) / 2;
        if (r < c) break;
        r -= c;
    }
    int j = i + 1;
    for (; j < 31; ++j) {
        int c = 31 - j;
        if (r < c) break;
        r -= c;
    }
    int k = j + 1 + r;
    g_idx[g] = make_int4(i, j, k, 0);
}

// ---------------- kernel A: rel_conv -> RC[g][b*16+f] ------------------------
// One warp handles 8 (b,g) cells. Lane = (f, h): filter f, half h of the 36
// float4 chunks. Filter fragment (18 float4 = 72 floats) lives in registers;
// the gathered 3x3x16 sub-tensor is broadcast from shared. FFMA-bound.
__global__ __launch_bounds__(256) void k_relconv(const float* __restrict__ inputs,
                                                 const float* __restrict__ filters) {
    const int warp = threadIdx.x >> 5;
    const int lane = threadIdx.x & 31;
    const int f = lane & 15, h = lane >> 4;

    // filters[f][a][c][d] : float4 index = f*36 + chunk, chunk = (a*3+c)*4 + d4
    const float4* f4 = (const float4*)filters;
    float4 fr[18];
#pragma unroll
    for (int u = 0; u < 18; ++u) fr[u] = f4[f * 36 + 2 * u + h];

    __shared__ float4 s_sub[8][36];
    const float4* in4 = (const float4*)inputs;

    long base = ((long)blockIdx.x * 8 + warp) * 8;
#pragma unroll 1
    for (int it = 0; it < 8; ++it) {
        int cell = (int)base + it;              // < 158720
        int b = cell / NG;
        int g = cell - b * NG;
        int4 id = g_idx[g];

        // gather 36 float4 = inputs[b, I[a], I[c], :] for the 9 (a,c) pairs
        {
            int ch = lane;                       // chunks 0..31
            int p = ch >> 2, c4 = ch & 3;
            int a = p / 3, c = p - a * 3;
            int ia = (a == 0) ? id.x : (a == 1) ? id.y : id.z;
            int ib = (c == 0) ? id.x : (c == 1) ? id.y : id.z;
            s_sub[warp][ch] = in4[((b * N_OBJ + ia) * N_OBJ + ib) * 4 + c4];
            if (lane < 4) {                      // chunks 32..35 (p=8 -> a=2,c=2)
                int ch2 = lane + 32;
                s_sub[warp][ch2] = in4[((b * N_OBJ + id.z) * N_OBJ + id.z) * 4 + (ch2 & 3)];
            }
        }
        __syncwarp();

        float acc = 0.f;
#pragma unroll
        for (int u = 0; u < 18; ++u) {
            float4 sv = s_sub[warp][2 * u + h];
            acc += sv.x * fr[u].x;
            acc += sv.y * fr[u].y;
            acc += sv.z * fr[u].z;
            acc += sv.w * fr[u].w;
        }
        acc += __shfl_xor_sync(0xFFFFFFFFu, acc, 16);
        if (h == 0) g_RC[g * NCOL + b * 16 + f] = acc;
        __syncwarp();
    }
}

// ---------------- kernel B: softplus -> triple product -> row softmax --------
__global__ __launch_bounds__(256) void k_weights(const float* __restrict__ logits) {
    __shared__ float s_sp[N_OBJ];
    __shared__ float s_w[NG];
    __shared__ float s_red[8];
    const int q = blockIdx.x;
    const int t = threadIdx.x;

    if (t < N_OBJ) {
        float x = logits[q * N_OBJ + t];
        s_sp[t] = fmaxf(x, 0.f) + log1pf(expf(-fabsf(x)));   // stable softplus
    }
    __syncthreads();

    float lmax = -1e30f;
    for (int g = t; g < NG; g += 256) {
        int4 id = g_idx[g];
        float w = s_sp[id.x] * s_sp[id.y] * s_sp[id.z];      // BETA = 1.0
        s_w[g] = w;
        lmax = fmaxf(lmax, w);
    }
#pragma unroll
    for (int o = 16; o; o >>= 1) lmax = fmaxf(lmax, __shfl_xor_sync(0xFFFFFFFFu, lmax, o));
    if ((t & 31) == 0) s_red[t >> 5] = lmax;
    __syncthreads();
    float bmax = s_red[0];
#pragma unroll
    for (int w = 1; w < 8; ++w) bmax = fmaxf(bmax, s_red[w]);
    __syncthreads();

    float lsum = 0.f;
    for (int g = t; g < NG; g += 256) {
        float e = __expf(s_w[g] - bmax);
        s_w[g] = e;
        lsum += e;
    }
#pragma unroll
    for (int o = 16; o; o >>= 1) lsum += __shfl_xor_sync(0xFFFFFFFFu, lsum, o);
    if ((t & 31) == 0) s_red[t >> 5] = lsum;
    __syncthreads();
    float bsum = 0.f;
#pragma unroll
    for (int w = 0; w < 8; ++w) bsum += s_red[w];
    float inv = 1.0f / bsum;

    for (int g = t; g < NG; g += 256) g_W[q * NG + g] = s_w[g] * inv;
}

// ---------------- kernel C: SGEMM 512(q) x 512(col) x 4960(g), split-K=4 -----
// out2[q][col] = sum_g W[q][g] * RC[g][col].  BM=BN=64, BK=16, TM=TN=4,
// 256 threads, FFMA2 (fma.rn.f32x2) inner product. Partials to g_part.
__global__ __launch_bounds__(256) void k_gemm() {
    __shared__ float As[16][64];   // [k][m]
    __shared__ float Bs[16][64];   // [k][n]
    const int t = threadIdx.x;
    const int tx = t & 15, ty = t >> 4;
    const int m0 = blockIdx.y * 64, n0 = blockIdx.x * 64;
    const int z = blockIdx.z;
    const int tt0 = z * 78;
    const int tt1 = min(KTILES, tt0 + 78);

    unsigned long long acc[4][2];
#pragma unroll
    for (int i = 0; i < 4; ++i) { acc[i][0] = 0ull; acc[i][1] = 0ull; }

    const float4* W4 = (const float4*)g_W;   // row = 1240 float4
    const float4* R4 = (const float4*)g_RC;  // row = 128 float4
    const int lm  = t >> 2, lkq = t & 3;     // A-load: 64 rows x 4 float4
    const int lr  = t >> 4, ln4 = t & 15;    // B-load: 16 rows x 16 float4

    for (int tt = tt0; tt < tt1; ++tt) {
        int k0 = tt * 16;
        float4 wa = W4[(m0 + lm) * 1240 + (k0 >> 2) + lkq];
        float4 bb = R4[(k0 + lr) * 128 + (n0 >> 2) + ln4];
        __syncthreads();
        As[lkq * 4 + 0][lm] = wa.x;
        As[lkq * 4 + 1][lm] = wa.y;
        As[lkq * 4 + 2][lm] = wa.z;
        As[lkq * 4 + 3][lm] = wa.w;
        *(float4*)&Bs[lr][ln4 * 4] = bb;
        __syncthreads();
#pragma unroll
        for (int k = 0; k < 16; ++k) {
            float4 av = *(const float4*)&As[k][ty * 4];
            ulonglong2 bu = *(const ulonglong2*)&Bs[k][tx * 4];
            unsigned long long a0 = dup2(av.x), a1 = dup2(av.y);
            unsigned long long a2 = dup2(av.z), a3 = dup2(av.w);
            ffma2(acc[0][0], a0, bu.x); ffma2(acc[0][1], a0, bu.y);
            ffma2(acc[1][0], a1, bu.x); ffma2(acc[1][1], a1, bu.y);
            ffma2(acc[2][0], a2, bu.x); ffma2(acc[2][1], a2, bu.y);
            ffma2(acc[3][0], a3, bu.x); ffma2(acc[3][1], a3, bu.y);
        }
    }

    float* P = g_part + z * (NQ * NCOL);
#pragma unroll
    for (int i = 0; i < 4; ++i) {
        int m = m0 + ty * 4 + i;
        float2 v0 = unpk2(acc[i][0]);
        float2 v1 = unpk2(acc[i][1]);
        float4 o = make_float4(v0.x, v0.y, v1.x, v1.y);
        *(float4*)&P[m * NCOL + n0 + tx * 4] = o;
    }
}

// ---------------- kernel D: reduce split-K partials + scatter to out ---------
__global__ void k_reduce(float* __restrict__ out) {
    int t = blockIdx.x * blockDim.x + threadIdx.x;
    if (t >= OUT_ELEMS) return;
    float s = g_part[t] + g_part[t + OUT_ELEMS] +
              g_part[t + 2 * OUT_ELEMS] + g_part[t + 3 * OUT_ELEMS];
    int q = t >> 9, col = t & 511;
    int b = col >> 4, f = col & 15;
    out[(b * NQ + q) * NFILT + f] = s;   // out[b][q][f]
}

// ---------------- launch -----------------------------------------------------
extern "C" void kernel_launch(void* const* d_in, const int* in_sizes, int n_in,
                              void* d_out, int out_size) {
    const float *inputs = nullptr, *logits = nullptr, *filts = nullptr;
    for (int i = 0; i < n_in; ++i) {
        if (in_sizes[i] == BATCH * N_OBJ * N_OBJ * RDIM) inputs = (const float*)d_in[i];
        else if (in_sizes[i] == NQ * N_OBJ)              logits = (const float*)d_in[i];
        else if (in_sizes[i] == NFILT * GSIZE * GSIZE * RDIM) filts = (const float*)d_in[i];
    }
    float* out = (float*)d_out;

    k_idx<<<20, 256>>>();
    k_relconv<<<2480, 256>>>(inputs, filts);     // 2480*8 warps * 8 cells = 158720
    k_weights<<<NQ, 256>>>(logits);
    k_gemm<<<dim3(8, 8, NSPLIT), 256>>>();
    k_reduce<<<(OUT_ELEMS + 511) / 512, 512>>>(out);
}

// round 2
// speedup vs baseline: 1.1071x; 1.1071x over previous
#include <cuda_runtime.h>
#include <cuda_bf16.h>

#define N_OBJ 32
#define GSIZE 3
#define NFILT 16
#define RDIM 16
#define BATCH 32
#define NQ 512
#define NG 4960                 // C(32,3)
#define NCOL 512                // BATCH * NFILT
#define OUT_ELEMS (BATCH * NQ * NFILT)   // 262144
#define NSPLIT 31               // 310 k-tiles / 31 = 10 per CTA, exact
#define KTILES 310              // 4960 / 16

// ---------------- scratch (device globals; no allocations allowed) ------------
__device__ float  g_RC[NG * NCOL];            // rel_conv [g][b*16+f]   (10.2 MB)
__device__ float  g_W [NQ * NG];              // softmax weights [q][g] (10.2 MB)
__device__ float  g_part[NSPLIT * NQ * NCOL]; // split-K partials       (32.5 MB)
__device__ int4   g_idx[NG];                  // combination table (i<j<k)

// ---------------- packed fp32x2 helpers --------------------------------------
__device__ __forceinline__ void ffma2(unsigned long long &acc,
                                      unsigned long long a,
                                      unsigned long long b) {
    asm("fma.rn.f32x2 %0, %1, %2, %0;" : "+l"(acc) : "l"(a), "l"(b));
}
__device__ __forceinline__ unsigned long long dup2(float x) {
    unsigned long long r;
    asm("mov.b64 %0, {%1, %1};" : "=l"(r) : "f"(x));
    return r;
}
__device__ __forceinline__ float2 unpk2(unsigned long long v) {
    float2 r;
    asm("mov.b64 {%0, %1}, %2;" : "=f"(r.x), "=f"(r.y) : "l"(v));
    return r;
}

// ---------------- kernel 0: lexicographic unrank of C(32,3) ------------------
__global__ void k_idx() {
    int g = blockIdx.x * blockDim.x + threadIdx.x;
    if (g >= NG) return;
    int r = g, i = 0;
    for (; i < 30; ++i) {
        int c = (31 - i) * (30 - i) / 2;
        if (r < c) break;
        r -= c;
    }
    int j = i + 1;
    for (; j < 31; ++j) {
        int c = 31 - j;
        if (r < c) break;
        r -= c;
    }
    int k = j + 1 + r;
    g_idx[g] = make_int4(i, j, k, 0);
}

// ---------------- kernel A: rel_conv -> RC[g][b*16+f] ------------------------
__global__ __launch_bounds__(256) void k_relconv(const float* __restrict__ inputs,
                                                 const float* __restrict__ filters) {
    const int warp = threadIdx.x >> 5;
    const int lane = threadIdx.x & 31;
    const int f = lane & 15, h = lane >> 4;

    const float4* f4 = (const float4*)filters;
    float4 fr[18];
#pragma unroll
    for (int u = 0; u < 18; ++u) fr[u] = f4[f * 36 + 2 * u + h];

    __shared__ float4 s_sub[8][36];
    const float4* in4 = (const float4*)inputs;

    long base = ((long)blockIdx.x * 8 + warp) * 8;
#pragma unroll 1
    for (int it = 0; it < 8; ++it) {
        int cell = (int)base + it;              // < 158720
        int b = cell / NG;
        int g = cell - b * NG;
        int4 id = g_idx[g];

        {
            int ch = lane;                       // chunks 0..31
            int p = ch >> 2, c4 = ch & 3;
            int a = p / 3, c = p - a * 3;
            int ia = (a == 0) ? id.x : (a == 1) ? id.y : id.z;
            int ib = (c == 0) ? id.x : (c == 1) ? id.y : id.z;
            s_sub[warp][ch] = in4[((b * N_OBJ + ia) * N_OBJ + ib) * 4 + c4];
            if (lane < 4) {                      // chunks 32..35 (a=2,c=2)
                int ch2 = lane + 32;
                s_sub[warp][ch2] = in4[((b * N_OBJ + id.z) * N_OBJ + id.z) * 4 + (ch2 & 3)];
            }
        }
        __syncwarp();

        float acc = 0.f;
#pragma unroll
        for (int u = 0; u < 18; ++u) {
            float4 sv = s_sub[warp][2 * u + h];
            acc += sv.x * fr[u].x;
            acc += sv.y * fr[u].y;
            acc += sv.z * fr[u].z;
            acc += sv.w * fr[u].w;
        }
        acc += __shfl_xor_sync(0xFFFFFFFFu, acc, 16);
        if (h == 0) g_RC[g * NCOL + b * 16 + f] = acc;
        __syncwarp();
    }
}

// ---------------- kernel B: softplus -> triple product -> row softmax --------
__global__ __launch_bounds__(256) void k_weights(const float* __restrict__ logits) {
    __shared__ float s_sp[N_OBJ];
    __shared__ float s_w[NG];
    __shared__ float s_red[8];
    const int q = blockIdx.x;
    const int t = threadIdx.x;

    if (t < N_OBJ) {
        float x = logits[q * N_OBJ + t];
        s_sp[t] = fmaxf(x, 0.f) + log1pf(expf(-fabsf(x)));
    }
    __syncthreads();

    float lmax = -1e30f;
    for (int g = t; g < NG; g += 256) {
        int4 id = g_idx[g];
        float w = s_sp[id.x] * s_sp[id.y] * s_sp[id.z];
        s_w[g] = w;
        lmax = fmaxf(lmax, w);
    }
#pragma unroll
    for (int o = 16; o; o >>= 1) lmax = fmaxf(lmax, __shfl_xor_sync(0xFFFFFFFFu, lmax, o));
    if ((t & 31) == 0) s_red[t >> 5] = lmax;
    __syncthreads();
    float bmax = s_red[0];
#pragma unroll
    for (int w = 1; w < 8; ++w) bmax = fmaxf(bmax, s_red[w]);
    __syncthreads();

    float lsum = 0.f;
    for (int g = t; g < NG; g += 256) {
        float e = __expf(s_w[g] - bmax);
        s_w[g] = e;
        lsum += e;
    }
#pragma unroll
    for (int o = 16; o; o >>= 1) lsum += __shfl_xor_sync(0xFFFFFFFFu, lsum, o);
    if ((t & 31) == 0) s_red[t >> 5] = lsum;
    __syncthreads();
    float bsum = 0.f;
#pragma unroll
    for (int w = 0; w < 8; ++w) bsum += s_red[w];
    float inv = 1.0f / bsum;

    for (int g = t; g < NG; g += 256) g_W[q * NG + g] = s_w[g] * inv;
}

// ---------------- kernel C: SGEMM 512(q) x 512(col) x 4960(g), split-K=31 ----
// BM=BN=128, BK=16, 256 threads, TM=TN=8, FFMA2 inner product.
// Per CTA: exactly 10 k-tiles. Partials to g_part (reduced by k_reduce).
__global__ __launch_bounds__(256, 2) void k_gemm() {
    __shared__ float As[16][128];   // [k][m]
    __shared__ float Bs[16][128];   // [k][n]
    const int t  = threadIdx.x;
    const int tx = t & 15;          // n subtile
    const int ty = t >> 4;          // m subtile
    const int m0 = blockIdx.y * 128, n0 = blockIdx.x * 128;
    const int z  = blockIdx.z;
    const int tt0 = z * 10, tt1 = tt0 + 10;

    unsigned long long acc[8][4];
#pragma unroll
    for (int i = 0; i < 8; ++i)
#pragma unroll
        for (int j = 0; j < 4; ++j) acc[i][j] = 0ull;

    const float4* W4 = (const float4*)g_W;   // row stride 1240 float4
    const float4* R4 = (const float4*)g_RC;  // row stride 128 float4

    // A: 128 rows x 4 float4 (=16 k) -> 512 float4, 2 per thread
    const int ar = t >> 2, aq = t & 3;       // rows t>>2 and t>>2 + 64
    // B: 16 rows x 32 float4 -> 512 float4, 2 per thread
    const int br = t >> 5, bn = t & 31;      // k-rows br and br+8

    for (int tt = tt0; tt < tt1; ++tt) {
        int k0 = tt * 16;
        float4 a0 = W4[(m0 + ar)      * 1240 + (k0 >> 2) + aq];
        float4 a1 = W4[(m0 + ar + 64) * 1240 + (k0 >> 2) + aq];
        float4 b0 = R4[(k0 + br)     * 128 + (n0 >> 2) + bn];
        float4 b1 = R4[(k0 + br + 8) * 128 + (n0 >> 2) + bn];
        __syncthreads();
        As[aq * 4 + 0][ar] = a0.x;
        As[aq * 4 + 1][ar] = a0.y;
        As[aq * 4 + 2][ar] = a0.z;
        As[aq * 4 + 3][ar] = a0.w;
        As[aq * 4 + 0][ar + 64] = a1.x;
        As[aq * 4 + 1][ar + 64] = a1.y;
        As[aq * 4 + 2][ar + 64] = a1.z;
        As[aq * 4 + 3][ar + 64] = a1.w;
        *(float4*)&Bs[br][bn * 4]     = b0;
        *(float4*)&Bs[br + 8][bn * 4] = b1;
        __syncthreads();
#pragma unroll
        for (int k = 0; k < 16; ++k) {
            float4 av0 = *(const float4*)&As[k][ty * 8];
            float4 av1 = *(const float4*)&As[k][ty * 8 + 4];
            ulonglong2 bu0 = *(const ulonglong2*)&Bs[k][tx * 8];
            ulonglong2 bu1 = *(const ulonglong2*)&Bs[k][tx * 8 + 4];
            unsigned long long ad[8];
            ad[0] = dup2(av0.x); ad[1] = dup2(av0.y);
            ad[2] = dup2(av0.z); ad[3] = dup2(av0.w);
            ad[4] = dup2(av1.x); ad[5] = dup2(av1.y);
            ad[6] = dup2(av1.z); ad[7] = dup2(av1.w);
#pragma unroll
            for (int i = 0; i < 8; ++i) {
                ffma2(acc[i][0], ad[i], bu0.x);
                ffma2(acc[i][1], ad[i], bu0.y);
                ffma2(acc[i][2], ad[i], bu1.x);
                ffma2(acc[i][3], ad[i], bu1.y);
            }
        }
    }

    float* P = g_part + (long)z * (NQ * NCOL);
#pragma unroll
    for (int i = 0; i < 8; ++i) {
        int m = m0 + ty * 8 + i;
        float2 v0 = unpk2(acc[i][0]);
        float2 v1 = unpk2(acc[i][1]);
        float2 v2 = unpk2(acc[i][2]);
        float2 v3 = unpk2(acc[i][3]);
        float4 o0 = make_float4(v0.x, v0.y, v1.x, v1.y);
        float4 o1 = make_float4(v2.x, v2.y, v3.x, v3.y);
        *(float4*)&P[m * NCOL + n0 + tx * 8]     = o0;
        *(float4*)&P[m * NCOL + n0 + tx * 8 + 4] = o1;
    }
}

// ---------------- kernel D: reduce split-K partials + scatter to out ---------
__global__ void k_reduce(float* __restrict__ out) {
    int t = blockIdx.x * blockDim.x + threadIdx.x;
    if (t >= OUT_ELEMS) return;
    float s = 0.f;
#pragma unroll
    for (int j = 0; j < NSPLIT; ++j)
        s += g_part[(long)j * OUT_ELEMS + t];
    int q = t >> 9, col = t & 511;
    int b = col >> 4, f = col & 15;
    out[(b * NQ + q) * NFILT + f] = s;   // out[b][q][f]
}

// ---------------- launch -----------------------------------------------------
extern "C" void kernel_launch(void* const* d_in, const int* in_sizes, int n_in,
                              void* d_out, int out_size) {
    const float *inputs = nullptr, *logits = nullptr, *filts = nullptr;
    for (int i = 0; i < n_in; ++i) {
        if (in_sizes[i] == BATCH * N_OBJ * N_OBJ * RDIM) inputs = (const float*)d_in[i];
        else if (in_sizes[i] == NQ * N_OBJ)              logits = (const float*)d_in[i];
        else if (in_sizes[i] == NFILT * GSIZE * GSIZE * RDIM) filts = (const float*)d_in[i];
    }
    float* out = (float*)d_out;

    k_idx<<<20, 256>>>();
    k_relconv<<<2480, 256>>>(inputs, filts);
    k_weights<<<NQ, 256>>>(logits);
    k_gemm<<<dim3(4, 4, NSPLIT), 256>>>();
    k_reduce<<<(OUT_ELEMS + 511) / 512, 512>>>(out);
}

// round 4
// speedup vs baseline: 1.1215x; 1.0130x over previous
#include <cuda_runtime.h>
#include <cuda_bf16.h>
#include <cstdint>

#define N_OBJ 32
#define NFILT 16
#define RDIM 16
#define BATCH 32
#define NQ 512
#define NG 4960                  // C(32,3)
#define NCOL 512                 // BATCH * NFILT
#define OUT_ELEMS (NQ * NCOL)    // 262144
#define KP 14880                 // K' = 3*NG, = 465 * 32 exactly
#define NSPLIT 15
#define ITERS 31                 // 465 / 15
#define BK 32
#define LDSW 40                  // smem row stride in halves (80B, conflict-free ldmatrix)

// ---------------- scratch (device globals) -----------------------------------
__device__ __nv_bfloat16 g_Wb [NQ   * KP];        // A' [q][k']   (15.2 MB)
__device__ __nv_bfloat16 g_RCb[NCOL * KP];        // B' [col][k'] (15.2 MB)
__device__ float         g_part[NSPLIT * OUT_ELEMS];
__device__ int4          g_idx[NG];

// ---------------- helpers ----------------------------------------------------
__device__ __forceinline__ uint32_t smem_u32(const void* p) {
    uint32_t a;
    asm("{ .reg .u64 t; cvta.to.shared.u64 t, %1; cvt.u32.u64 %0, t; }" : "=r"(a) : "l"(p));
    return a;
}
__device__ __forceinline__ void ldmx4(uint32_t r[4], uint32_t addr) {
    asm volatile("ldmatrix.sync.aligned.m8n8.x4.shared.b16 {%0,%1,%2,%3}, [%4];"
                 : "=r"(r[0]), "=r"(r[1]), "=r"(r[2]), "=r"(r[3]) : "r"(addr));
}
__device__ __forceinline__ void mma_bf16(float c[4], const uint32_t a[4],
                                         uint32_t b0, uint32_t b1) {
    asm volatile("mma.sync.aligned.m16n8k16.row.col.f32.bf16.bf16.f32 "
                 "{%0,%1,%2,%3}, {%4,%5,%6,%7}, {%8,%9}, {%0,%1,%2,%3};"
                 : "+f"(c[0]), "+f"(c[1]), "+f"(c[2]), "+f"(c[3])
                 : "r"(a[0]), "r"(a[1]), "r"(a[2]), "r"(a[3]), "r"(b0), "r"(b1));
}

// ---------------- kernel 0: unrank C(32,3) -----------------------------------
__global__ void k_idx() {
    int g = blockIdx.x * blockDim.x + threadIdx.x;
    if (g >= NG) return;
    int r = g, i = 0;
    for (; i < 30; ++i) { int c = (31 - i) * (30 - i) / 2; if (r < c) break; r -= c; }
    int j = i + 1;
    for (; j < 31; ++j) { int c = 31 - j; if (r < c) break; r -= c; }
    g_idx[g] = make_int4(i, j, j + 1 + r, 0);
}

// ---------------- kernel A: rel_conv -> B' triple [rh, rl, rh] ---------------
__global__ __launch_bounds__(256) void k_relconv(const float* __restrict__ inputs,
                                                 const float* __restrict__ filters) {
    const int warp = threadIdx.x >> 5;
    const int lane = threadIdx.x & 31;
    const int f = lane & 15, h = lane >> 4;

    const float4* f4 = (const float4*)filters;
    float4 fr[18];
#pragma unroll
    for (int u = 0; u < 18; ++u) fr[u] = f4[f * 36 + 2 * u + h];

    __shared__ float4 s_sub[8][36];
    const float4* in4 = (const float4*)inputs;

    long base = ((long)blockIdx.x * 8 + warp) * 8;
#pragma unroll 1
    for (int it = 0; it < 8; ++it) {
        int cell = (int)base + it;
        int b = cell / NG;
        int g = cell - b * NG;
        int4 id = g_idx[g];
        {
            int ch = lane;
            int p = ch >> 2, c4 = ch & 3;
            int a = p / 3, c = p - a * 3;
            int ia = (a == 0) ? id.x : (a == 1) ? id.y : id.z;
            int ib = (c == 0) ? id.x : (c == 1) ? id.y : id.z;
            s_sub[warp][ch] = in4[((b * N_OBJ + ia) * N_OBJ + ib) * 4 + c4];
            if (lane < 4) {
                int ch2 = lane + 32;
                s_sub[warp][ch2] = in4[((b * N_OBJ + id.z) * N_OBJ + id.z) * 4 + (ch2 & 3)];
            }
        }
        __syncwarp();
        float acc = 0.f;
#pragma unroll
        for (int u = 0; u < 18; ++u) {
            float4 sv = s_sub[warp][2 * u + h];
            acc += sv.x * fr[u].x + sv.y * fr[u].y + sv.z * fr[u].z + sv.w * fr[u].w;
        }
        acc += __shfl_xor_sync(0xFFFFFFFFu, acc, 16);
        if (h == 0) {
            __nv_bfloat16 hi = __float2bfloat16(acc);
            __nv_bfloat16 lo = __float2bfloat16(acc - __bfloat162float(hi));
            __nv_bfloat16* dst = g_RCb + (long)(b * 16 + f) * KP + 3 * g;
            dst[0] = hi; dst[1] = lo; dst[2] = hi;
        }
        __syncwarp();
    }
}

// ---------------- kernel B: weights -> A' triple [wh, wh, wl] ----------------
__global__ __launch_bounds__(256) void k_weights(const float* __restrict__ logits) {
    __shared__ float s_sp[N_OBJ];
    __shared__ float s_w[NG];
    __shared__ float s_red[8];
    const int q = blockIdx.x;
    const int t = threadIdx.x;

    if (t < N_OBJ) {
        float x = logits[q * N_OBJ + t];
        s_sp[t] = fmaxf(x, 0.f) + log1pf(expf(-fabsf(x)));
    }
    __syncthreads();

    float lmax = -1e30f;
    for (int g = t; g < NG; g += 256) {
        int4 id = g_idx[g];
        float w = s_sp[id.x] * s_sp[id.y] * s_sp[id.z];
        s_w[g] = w;
        lmax = fmaxf(lmax, w);
    }
#pragma unroll
    for (int o = 16; o; o >>= 1) lmax = fmaxf(lmax, __shfl_xor_sync(0xFFFFFFFFu, lmax, o));
    if ((t & 31) == 0) s_red[t >> 5] = lmax;
    __syncthreads();
    float bmax = s_red[0];
#pragma unroll
    for (int w = 1; w < 8; ++w) bmax = fmaxf(bmax, s_red[w]);
    __syncthreads();

    float lsum = 0.f;
    for (int g = t; g < NG; g += 256) {
        float e = __expf(s_w[g] - bmax);
        s_w[g] = e;
        lsum += e;
    }
#pragma unroll
    for (int o = 16; o; o >>= 1) lsum += __shfl_xor_sync(0xFFFFFFFFu, lsum, o);
    if ((t & 31) == 0) s_red[t >> 5] = lsum;
    __syncthreads();
    float bsum = 0.f;
#pragma unroll
    for (int w = 0; w < 8; ++w) bsum += s_red[w];
    float inv = 1.0f / bsum;

    for (int g = t; g < NG; g += 256) {
        float w = s_w[g] * inv;
        __nv_bfloat16 hi = __float2bfloat16(w);
        __nv_bfloat16 lo = __float2bfloat16(w - __bfloat162float(hi));
        __nv_bfloat16* dst = g_Wb + (long)q * KP + 3 * g;
        dst[0] = hi; dst[1] = hi; dst[2] = lo;
    }
}

// ---------------- kernel C: mma.sync bf16 GEMM 512x512x14880, split-K=15 -----
// BM=BN=128, BK=32, 8 warps as 2(m) x 4(n), warp tile 64x32 via m16n8k16.
__global__ __launch_bounds__(256, 2) void k_mma() {
    __shared__ __align__(16) __nv_bfloat16 sA[128 * LDSW];
    __shared__ __align__(16) __nv_bfloat16 sB[128 * LDSW];
    const int t = threadIdx.x, lane = t & 31, wid = t >> 5;
    const int wm = wid & 1, wn = wid >> 1;
    const int m0 = blockIdx.y * 128, n0 = blockIdx.x * 128;
    const long kbase = (long)blockIdx.z * ITERS * BK;

    float acc[4][4][4];
#pragma unroll
    for (int i = 0; i < 4; ++i)
#pragma unroll
        for (int j = 0; j < 4; ++j)
#pragma unroll
            for (int v = 0; v < 4; ++v) acc[i][j][v] = 0.f;

    const int grow = t >> 2, gq = t & 3;           // global->smem: 2 rows per thread
    const int lr = lane & 15, lh = lane >> 4;      // ldmatrix lane addressing
    const uint32_t aAd = smem_u32(sA) + (uint32_t)(((wm * 64 + lr) * LDSW + lh * 8) * 2);
    const uint32_t bAd = smem_u32(sB) + (uint32_t)(((wn * 32 + lr) * LDSW + lh * 8) * 2);

#pragma unroll 1
    for (int tt = 0; tt < ITERS; ++tt) {
        const long k0 = kbase + (long)tt * BK;
        uint4 va  = *(const uint4*)(g_Wb  + (long)(m0 + grow)      * KP + k0 + gq * 8);
        uint4 va2 = *(const uint4*)(g_Wb  + (long)(m0 + grow + 64) * KP + k0 + gq * 8);
        uint4 vb  = *(const uint4*)(g_RCb + (long)(n0 + grow)      * KP + k0 + gq * 8);
        uint4 vb2 = *(const uint4*)(g_RCb + (long)(n0 + grow + 64) * KP + k0 + gq * 8);
        __syncthreads();
        *(uint4*)(sA + grow * LDSW + gq * 8)        = va;
        *(uint4*)(sA + (grow + 64) * LDSW + gq * 8) = va2;
        *(uint4*)(sB + grow * LDSW + gq * 8)        = vb;
        *(uint4*)(sB + (grow + 64) * LDSW + gq * 8) = vb2;
        __syncthreads();
#pragma unroll
        for (int ks = 0; ks < 2; ++ks) {
            uint32_t af[4][4], bf[2][4];
#pragma unroll
            for (int mt = 0; mt < 4; ++mt)
                ldmx4(af[mt], aAd + mt * (16 * LDSW * 2) + ks * 32);
#pragma unroll
            for (int np = 0; np < 2; ++np)
                ldmx4(bf[np], bAd + np * (16 * LDSW * 2) + ks * 32);
#pragma unroll
            for (int mt = 0; mt < 4; ++mt)
#pragma unroll
                for (int nt = 0; nt < 4; ++nt)
                    mma_bf16(acc[mt][nt], af[mt], bf[nt >> 1][nt & 1],
                             bf[nt >> 1][(nt & 1) + 2]);
        }
    }

    float* P = g_part + (long)blockIdx.z * OUT_ELEMS;
    const int erow = lane >> 2, ecol = (lane & 3) * 2;
#pragma unroll
    for (int mt = 0; mt < 4; ++mt)
#pragma unroll
        for (int nt = 0; nt < 4; ++nt) {
            int m = m0 + wm * 64 + mt * 16 + erow;
            int n = n0 + wn * 32 + nt * 8 + ecol;
            *(float2*)&P[(long)m * NCOL + n]       = make_float2(acc[mt][nt][0], acc[mt][nt][1]);
            *(float2*)&P[(long)(m + 8) * NCOL + n] = make_float2(acc[mt][nt][2], acc[mt][nt][3]);
        }
}

// ---------------- kernel D: reduce split-K partials + scatter ----------------
__global__ void k_reduce(float* __restrict__ out) {
    int t = blockIdx.x * blockDim.x + threadIdx.x;
    if (t >= OUT_ELEMS) return;
    float s = 0.f;
#pragma unroll
    for (int j = 0; j < NSPLIT; ++j)
        s += g_part[(long)j * OUT_ELEMS + t];
    int q = t >> 9, col = t & 511;
    int b = col >> 4, f = col & 15;
    out[(b * NQ + q) * NFILT + f] = s;   // out[b][q][f]
}

// ---------------- launch -----------------------------------------------------
extern "C" void kernel_launch(void* const* d_in, const int* in_sizes, int n_in,
                              void* d_out, int out_size) {
    const float *inputs = nullptr, *logits = nullptr, *filts = nullptr;
    for (int i = 0; i < n_in; ++i) {
        if (in_sizes[i] == BATCH * N_OBJ * N_OBJ * RDIM) inputs = (const float*)d_in[i];
        else if (in_sizes[i] == NQ * N_OBJ)              logits = (const float*)d_in[i];
        else if (in_sizes[i] == NFILT * 3 * 3 * RDIM)    filts = (const float*)d_in[i];
    }
    float* out = (float*)d_out;

    k_idx<<<20, 256>>>();
    k_relconv<<<2480, 256>>>(inputs, filts);
    k_weights<<<NQ, 256>>>(logits);
    k_mma<<<dim3(4, 4, NSPLIT), 256>>>();
    k_reduce<<<(OUT_ELEMS + 511) / 512, 512>>>(out);
}

// round 5
// speedup vs baseline: 1.8290x; 1.6308x over previous
#include <cuda_runtime.h>
#include <cuda_bf16.h>
#include <cstdint>

#define N_OBJ 32
#define NFILT 16
#define RDIM 16
#define BATCH 32
#define NQ 512
#define NG 4960                  // C(32,3)
#define NCOL 512                 // BATCH * NFILT
#define OUT_ELEMS (NQ * NCOL)    // 262144
#define KP 14880                 // K' = 3*NG = 465 * 32 exactly
#define NSPLIT 31
#define ITERS 15                 // 465 / 31
#define BK 32
#define LDSW 40                  // smem row stride (halves); 80B rows, ldmatrix-safe
#define GCHUNK 248               // 4960 = 20 * 248

// ---------------- scratch (device globals) -----------------------------------
__device__ float         g_P  [BATCH * 9 * 1024 * 16];   // P[b][ac][i*32+j][f] 18.9MB
__device__ __nv_bfloat16 g_Wb [NQ   * KP];               // A' [q][k']
__device__ __nv_bfloat16 g_RCb[NCOL * KP];               // B' [col][k']
__device__ float         g_part[NSPLIT * OUT_ELEMS];
__device__ int4          g_idx[NG];

// ---------------- helpers ----------------------------------------------------
__device__ __forceinline__ uint32_t smem_u32(const void* p) {
    uint32_t a;
    asm("{ .reg .u64 t; cvta.to.shared.u64 t, %1; cvt.u32.u64 %0, t; }" : "=r"(a) : "l"(p));
    return a;
}
__device__ __forceinline__ void ldmx4(uint32_t r[4], uint32_t addr) {
    asm volatile("ldmatrix.sync.aligned.m8n8.x4.shared.b16 {%0,%1,%2,%3}, [%4];"
                 : "=r"(r[0]), "=r"(r[1]), "=r"(r[2]), "=r"(r[3]) : "r"(addr));
}
__device__ __forceinline__ void mma_bf16(float c[4], const uint32_t a[4],
                                         uint32_t b0, uint32_t b1) {
    asm volatile("mma.sync.aligned.m16n8k16.row.col.f32.bf16.bf16.f32 "
                 "{%0,%1,%2,%3}, {%4,%5,%6,%7}, {%8,%9}, {%0,%1,%2,%3};"
                 : "+f"(c[0]), "+f"(c[1]), "+f"(c[2]), "+f"(c[3])
                 : "r"(a[0]), "r"(a[1]), "r"(a[2]), "r"(a[3]), "r"(b0), "r"(b1));
}
#define CP_ASYNC16(dst, src) \
    asm volatile("cp.async.cg.shared.global [%0], [%1], 16;" :: "r"(dst), "l"(src) : "memory")
#define CP_COMMIT() asm volatile("cp.async.commit_group;" ::: "memory")
#define CP_WAIT(n)  asm volatile("cp.async.wait_group %0;" :: "n"(n) : "memory")

// ---------------- kernel 0: unrank C(32,3) -----------------------------------
__global__ void k_idx() {
    int g = blockIdx.x * blockDim.x + threadIdx.x;
    if (g >= NG) return;
    int r = g, i = 0;
    for (; i < 30; ++i) { int c = (31 - i) * (30 - i) / 2; if (r < c) break; r -= c; }
    int j = i + 1;
    for (; j < 31; ++j) { int c = 31 - j; if (r < c) break; r -= c; }
    g_idx[g] = make_int4(i, j, j + 1 + r, 0);
}

// ---------------- kernel P: pair conv  P[b][ac][ij][f] -----------------------
// grid (128, 3): 256 threads, thread = (b, i, j); blockIdx.y covers 3 ac each.
__global__ __launch_bounds__(256) void k_pairconv(const float* __restrict__ inputs,
                                                  const float* __restrict__ filters) {
    __shared__ float4 s_sf[3 * 16 * 4];      // [acl][d][f4]
    const int t = threadIdx.x;
    const int ac0 = blockIdx.y * 3;
#pragma unroll
    for (int u = 0; u < 3; ++u) {
        int idx = t + u * 256;               // < 768
        int acl = idx >> 8, r = idx & 255;
        int d = r >> 4, f = r & 15;
        ((float*)s_sf)[(acl * 16 + d) * 16 + f] =
            filters[(f * 9 + ac0 + acl) * 16 + d];
    }
    __syncthreads();

    const int cell = blockIdx.x * 256 + t;   // (b, ij) in [0, 32768)
    const float4* rv4 = (const float4*)(inputs + (long)cell * 16);
    float4 rv[4];
#pragma unroll
    for (int u = 0; u < 4; ++u) rv[u] = rv4[u];
    const float rs[16] = { rv[0].x, rv[0].y, rv[0].z, rv[0].w,
                           rv[1].x, rv[1].y, rv[1].z, rv[1].w,
                           rv[2].x, rv[2].y, rv[2].z, rv[2].w,
                           rv[3].x, rv[3].y, rv[3].z, rv[3].w };
    const int b = cell >> 10, ij = cell & 1023;

#pragma unroll
    for (int acl = 0; acl < 3; ++acl) {
        float4 acc[4] = { {0,0,0,0}, {0,0,0,0}, {0,0,0,0}, {0,0,0,0} };
#pragma unroll
        for (int d = 0; d < 16; ++d) {
            float xv = rs[d];
#pragma unroll
            for (int f4 = 0; f4 < 4; ++f4) {
                float4 sf = s_sf[(acl * 16 + d) * 4 + f4];
                acc[f4].x += xv * sf.x; acc[f4].y += xv * sf.y;
                acc[f4].z += xv * sf.z; acc[f4].w += xv * sf.w;
            }
        }
        float4* dst = (float4*)(g_P + ((long)(b * 9 + ac0 + acl) * 1024 + ij) * 16);
#pragma unroll
        for (int f4 = 0; f4 < 4; ++f4) dst[f4] = acc[f4];
    }
}

// ---------------- kernel A: assemble rel_conv + split -> B' [col][k'] --------
// grid (20, 32): blockIdx.y = b, 248 active threads = g within chunk.
__global__ __launch_bounds__(256) void k_rcasm() {
    __shared__ __nv_bfloat16 s_t[16][3 * GCHUNK];   // 16 rows x 744 bf16
    const int t = threadIdx.x;
    const int b = blockIdx.y, chunk = blockIdx.x;

    if (t < GCHUNK) {
        const int g = chunk * GCHUNK + t;
        const int4 id = g_idx[g];
        const int ia[3] = { id.x, id.y, id.z };
        float4 acc[4] = { {0,0,0,0}, {0,0,0,0}, {0,0,0,0}, {0,0,0,0} };
#pragma unroll
        for (int a = 0; a < 3; ++a)
#pragma unroll
            for (int c = 0; c < 3; ++c) {
                const float4* p = (const float4*)(g_P +
                    ((long)(b * 9 + a * 3 + c) * 1024 + ia[a] * 32 + ia[c]) * 16);
#pragma unroll
                for (int f4 = 0; f4 < 4; ++f4) {
                    float4 v = p[f4];
                    acc[f4].x += v.x; acc[f4].y += v.y;
                    acc[f4].z += v.z; acc[f4].w += v.w;
                }
            }
        const float* af = (const float*)acc;
#pragma unroll
        for (int f = 0; f < 16; ++f) {
            float x = af[f];
            __nv_bfloat16 hi = __float2bfloat16(x);
            __nv_bfloat16 lo = __float2bfloat16(x - __bfloat162float(hi));
            s_t[f][3 * t]     = hi;
            s_t[f][3 * t + 1] = lo;
            s_t[f][3 * t + 2] = hi;
        }
    }
    __syncthreads();

    // coalesced copy out: 16 rows x 744 bf16 (= 372 u32 each)
#pragma unroll 1
    for (int r = 0; r < 16; ++r) {
        const uint32_t* src = (const uint32_t*)&s_t[r][0];
        uint32_t* dst = (uint32_t*)(g_RCb + (long)(b * 16 + r) * KP + chunk * (3 * GCHUNK));
        for (int idx = t; idx < (3 * GCHUNK) / 2; idx += 256) dst[idx] = src[idx];
    }
}

// ---------------- kernel B: weights -> A' triple [wh, wh, wl] ----------------
__global__ __launch_bounds__(256) void k_weights(const float* __restrict__ logits) {
    __shared__ float s_sp[N_OBJ];
    __shared__ float s_w[NG];
    __shared__ float s_red[8];
    const int q = blockIdx.x;
    const int t = threadIdx.x;

    if (t < N_OBJ) {
        float x = logits[q * N_OBJ + t];
        s_sp[t] = fmaxf(x, 0.f) + log1pf(expf(-fabsf(x)));
    }
    __syncthreads();

    float lmax = -1e30f;
    for (int g = t; g < NG; g += 256) {
        int4 id = g_idx[g];
        float w = s_sp[id.x] * s_sp[id.y] * s_sp[id.z];
        s_w[g] = w;
        lmax = fmaxf(lmax, w);
    }
#pragma unroll
    for (int o = 16; o; o >>= 1) lmax = fmaxf(lmax, __shfl_xor_sync(0xFFFFFFFFu, lmax, o));
    if ((t & 31) == 0) s_red[t >> 5] = lmax;
    __syncthreads();
    float bmax = s_red[0];
#pragma unroll
    for (int w = 1; w < 8; ++w) bmax = fmaxf(bmax, s_red[w]);
    __syncthreads();

    float lsum = 0.f;
    for (int g = t; g < NG; g += 256) {
        float e = __expf(s_w[g] - bmax);
        s_w[g] = e;
        lsum += e;
    }
#pragma unroll
    for (int o = 16; o; o >>= 1) lsum += __shfl_xor_sync(0xFFFFFFFFu, lsum, o);
    if ((t & 31) == 0) s_red[t >> 5] = lsum;
    __syncthreads();
    float bsum = 0.f;
#pragma unroll
    for (int w = 0; w < 8; ++w) bsum += s_red[w];
    float inv = 1.0f / bsum;

    for (int g = t; g < NG; g += 256) {
        float w = s_w[g] * inv;
        __nv_bfloat16 hi = __float2bfloat16(w);
        __nv_bfloat16 lo = __float2bfloat16(w - __bfloat162float(hi));
        __nv_bfloat16* dst = g_Wb + (long)q * KP + 3 * g;
        dst[0] = hi; dst[1] = hi; dst[2] = lo;
    }
}

// ---------------- kernel C: bf16 HMMA GEMM, cp.async double-buffered ---------
// 512x512xKP, split-K=31 (15 iters). BM=BN=128, BK=32, 8 warps 2(m)x4(n).
__global__ __launch_bounds__(256, 2) void k_mma() {
    __shared__ __align__(16) __nv_bfloat16 sA[2][128 * LDSW];
    __shared__ __align__(16) __nv_bfloat16 sB[2][128 * LDSW];
    const int t = threadIdx.x, lane = t & 31, wid = t >> 5;
    const int wm = wid & 1, wn = wid >> 1;
    const int m0 = blockIdx.y * 128, n0 = blockIdx.x * 128;
    const long kbase = (long)blockIdx.z * ITERS * BK;

    float acc[4][4][4];
#pragma unroll
    for (int i = 0; i < 4; ++i)
#pragma unroll
        for (int j = 0; j < 4; ++j)
#pragma unroll
            for (int v = 0; v < 4; ++v) acc[i][j][v] = 0.f;

    const int grow = t >> 2, gq = t & 3;
    const uint32_t sA0 = smem_u32(sA), sB0 = smem_u32(sB);
    const uint32_t BUFB = 128 * LDSW * 2;   // bytes per buffer
    const uint32_t dA0 = sA0 + (uint32_t)((grow * LDSW + gq * 8) * 2);
    const uint32_t dA1 = dA0 + (uint32_t)(64 * LDSW * 2);
    const uint32_t dB0 = sB0 + (uint32_t)((grow * LDSW + gq * 8) * 2);
    const uint32_t dB1 = dB0 + (uint32_t)(64 * LDSW * 2);

    const int lr = lane & 15, lh = lane >> 4;
    const uint32_t aBase = sA0 + (uint32_t)(((wm * 64 + lr) * LDSW + lh * 8) * 2);
    const uint32_t bBase = sB0 + (uint32_t)(((wn * 32 + lr) * LDSW + lh * 8) * 2);

    // prologue: load tile 0 into buffer 0
    {
        const long k0 = kbase;
        CP_ASYNC16(dA0, g_Wb  + (long)(m0 + grow)      * KP + k0 + gq * 8);
        CP_ASYNC16(dA1, g_Wb  + (long)(m0 + grow + 64) * KP + k0 + gq * 8);
        CP_ASYNC16(dB0, g_RCb + (long)(n0 + grow)      * KP + k0 + gq * 8);
        CP_ASYNC16(dB1, g_RCb + (long)(n0 + grow + 64) * KP + k0 + gq * 8);
        CP_COMMIT();
    }

#pragma unroll 1
    for (int tt = 0; tt < ITERS; ++tt) {
        if (tt + 1 < ITERS) {
            const long k0 = kbase + (long)(tt + 1) * BK;
            const uint32_t bo = ((tt + 1) & 1) * BUFB;
            CP_ASYNC16(dA0 + bo, g_Wb  + (long)(m0 + grow)      * KP + k0 + gq * 8);
            CP_ASYNC16(dA1 + bo, g_Wb  + (long)(m0 + grow + 64) * KP + k0 + gq * 8);
            CP_ASYNC16(dB0 + bo, g_RCb + (long)(n0 + grow)      * KP + k0 + gq * 8);
            CP_ASYNC16(dB1 + bo, g_RCb + (long)(n0 + grow + 64) * KP + k0 + gq * 8);
            CP_COMMIT();
            CP_WAIT(1);
        } else {
            CP_WAIT(0);
        }
        __syncthreads();

        const uint32_t bo = (tt & 1) * BUFB;
#pragma unroll
        for (int ks = 0; ks < 2; ++ks) {
            uint32_t af[4][4], bf[2][4];
#pragma unroll
            for (int mt = 0; mt < 4; ++mt)
                ldmx4(af[mt], aBase + bo + mt * (16 * LDSW * 2) + ks * 32);
#pragma unroll
            for (int np = 0; np < 2; ++np)
                ldmx4(bf[np], bBase + bo + np * (16 * LDSW * 2) + ks * 32);
#pragma unroll
            for (int mt = 0; mt < 4; ++mt)
#pragma unroll
                for (int nt = 0; nt < 4; ++nt)
                    mma_bf16(acc[mt][nt], af[mt], bf[nt >> 1][nt & 1],
                             bf[nt >> 1][(nt & 1) + 2]);
        }
        __syncthreads();
    }

    float* P = g_part + (long)blockIdx.z * OUT_ELEMS;
    const int erow = lane >> 2, ecol = (lane & 3) * 2;
#pragma unroll
    for (int mt = 0; mt < 4; ++mt)
#pragma unroll
        for (int nt = 0; nt < 4; ++nt) {
            int m = m0 + wm * 64 + mt * 16 + erow;
            int n = n0 + wn * 32 + nt * 8 + ecol;
            *(float2*)&P[(long)m * NCOL + n]       = make_float2(acc[mt][nt][0], acc[mt][nt][1]);
            *(float2*)&P[(long)(m + 8) * NCOL + n] = make_float2(acc[mt][nt][2], acc[mt][nt][3]);
        }
}

// ---------------- kernel D: reduce split-K partials + scatter ----------------
__global__ void k_reduce(float* __restrict__ out) {
    int t = blockIdx.x * blockDim.x + threadIdx.x;
    if (t >= OUT_ELEMS) return;
    float s = 0.f;
#pragma unroll
    for (int j = 0; j < NSPLIT; ++j)
        s += g_part[(long)j * OUT_ELEMS + t];
    int q = t >> 9, col = t & 511;
    int b = col >> 4, f = col & 15;
    out[(b * NQ + q) * NFILT + f] = s;   // out[b][q][f]
}

// ---------------- launch -----------------------------------------------------
extern "C" void kernel_launch(void* const* d_in, const int* in_sizes, int n_in,
                              void* d_out, int out_size) {
    const float *inputs = nullptr, *logits = nullptr, *filts = nullptr;
    for (int i = 0; i < n_in; ++i) {
        if (in_sizes[i] == BATCH * N_OBJ * N_OBJ * RDIM) inputs = (const float*)d_in[i];
        else if (in_sizes[i] == NQ * N_OBJ)              logits = (const float*)d_in[i];
        else if (in_sizes[i] == NFILT * 3 * 3 * RDIM)    filts = (const float*)d_in[i];
    }
    float* out = (float*)d_out;

    k_idx<<<20, 256>>>();
    k_pairconv<<<dim3(128, 3), 256>>>(inputs, filts);
    k_weights<<<NQ, 256>>>(logits);
    k_rcasm<<<dim3(20, 32), 256>>>();
    k_mma<<<dim3(4, 4, NSPLIT), 256>>>();
    k_reduce<<<(OUT_ELEMS + 511) / 512, 512>>>(out);
}